// round 3
// baseline (speedup 1.0000x reference)
#include <cuda_runtime.h>

#define BS 16
#define D 448
#define HW 4096
#define NELEM (BS * D * HW)   // 29,360,128

// Packed fp32x2 FMA (Blackwell FFMA2): acc = a * b + acc, lane-wise on 2 packed fp32.
#define FMA2(accv, av, bv) \
    asm("fma.rn.f32x2 %0, %1, %2, %0;" : "+l"(accv) : "l"(av), "l"(bv))

// ---- scratch (allocation-free: device globals) ----
__device__ float g_WQVS[NELEM];            // W_q @ V_s  per batch  [b][d][h]
__device__ float g_WKVR[NELEM];            // W_k @ V_r  per batch  [b][d][h]
__device__ float g_WVVR[NELEM];            // W_v @ V_r  per batch  [b][d][h]
__device__ float g_scores[2 * BS * D * D]; // [neg][b][d][e], softmaxed in place
__device__ double g_Lsum;

__global__ void k_zero() { g_Lsum = 0.0; }

// ---------------------------------------------------------------------------
// Projection GEMMs: C[b][d][h] = sum_c W[d][c] * V[b][c][h]
// M=448(d) N=4096(h) K=448(c); 48 GEMMs (16 batches x 3 weights)
// A held duplicated in smem ({a,a} pairs) so FFMA2 needs no per-iter packing.
// ---------------------------------------------------------------------------
__global__ __launch_bounds__(256) void k_proj(const float* __restrict__ Vr,
                                              const float* __restrict__ Vs,
                                              const float* __restrict__ Wq,
                                              const float* __restrict__ Wk,
                                              const float* __restrict__ Wv) {
    const int bz = blockIdx.z;
    const int b = bz / 3, w = bz % 3;
    const float* W = (w == 0) ? Wq : ((w == 1) ? Wk : Wv);
    const float* V = ((w == 0) ? Vs : Vr) + (size_t)b * D * HW;
    float* C = ((w == 0) ? g_WQVS : ((w == 1) ? g_WKVR : g_WVVR)) + (size_t)b * D * HW;

    const int m0 = blockIdx.y * 64;  // d
    const int n0 = blockIdx.x * 64;  // h

    __shared__ float2 Asd[16][66];  // duplicated A: Asd[k][m] = {a, a}
    __shared__ float  Bs[16][64];   // Bs[k][n]

    const int t  = threadIdx.x;
    const int tx = t & 15, ty = t >> 4;
    const int a_m = t >> 2, a_k = (t & 3) * 4;   // A loader
    const int b_k = t >> 4, b_n = (t & 15) * 4;  // B loader

    unsigned long long acc[4][2] = {};  // [m][npair], packed fp32x2

    for (int k0 = 0; k0 < D; k0 += 16) {
        float4 av = *(const float4*)&W[(size_t)(m0 + a_m) * D + k0 + a_k];
        Asd[a_k + 0][a_m] = make_float2(av.x, av.x);
        Asd[a_k + 1][a_m] = make_float2(av.y, av.y);
        Asd[a_k + 2][a_m] = make_float2(av.z, av.z);
        Asd[a_k + 3][a_m] = make_float2(av.w, av.w);
        *(float4*)&Bs[b_k][b_n] = *(const float4*)&V[(size_t)(k0 + b_k) * HW + n0 + b_n];
        __syncthreads();
#pragma unroll
        for (int k = 0; k < 16; k++) {
            ulonglong2 a01 = *(const ulonglong2*)&Asd[k][ty * 4 + 0];
            ulonglong2 a23 = *(const ulonglong2*)&Asd[k][ty * 4 + 2];
            ulonglong2 bp  = *(const ulonglong2*)&Bs[k][tx * 4];
            FMA2(acc[0][0], a01.x, bp.x); FMA2(acc[0][1], a01.x, bp.y);
            FMA2(acc[1][0], a01.y, bp.x); FMA2(acc[1][1], a01.y, bp.y);
            FMA2(acc[2][0], a23.x, bp.x); FMA2(acc[2][1], a23.x, bp.y);
            FMA2(acc[3][0], a23.y, bp.x); FMA2(acc[3][1], a23.y, bp.y);
        }
        __syncthreads();
    }
#pragma unroll
    for (int i = 0; i < 4; i++) {
        float2 lo = *(const float2*)&acc[i][0];
        float2 hi = *(const float2*)&acc[i][1];
        float4 o = make_float4(lo.x, lo.y, hi.x, hi.y);
        *(float4*)&C[(size_t)(m0 + ty * 4 + i) * HW + n0 + tx * 4] = o;
    }
}

// ---------------------------------------------------------------------------
// Score GEMMs (NT): scores[neg][b][d][e] = (1/sqrt(D)) * sum_h Q[b][d][h] * K[b'][e][h]
// b' = b for pos, (b+1)%16 for neg.  M=N=448, K=4096.
// ---------------------------------------------------------------------------
__global__ __launch_bounds__(256) void k_scores() {
    const int bz = blockIdx.z;
    const int b = bz >> 1, neg = bz & 1;
    const int bk = neg ? ((b + 1) & (BS - 1)) : b;
    const float* A = g_WQVS + (size_t)b * D * HW;
    const float* B = g_WKVR + (size_t)bk * D * HW;
    float* C = g_scores + ((size_t)neg * BS + b) * D * D;

    const int m0 = blockIdx.y * 64;  // d
    const int n0 = blockIdx.x * 64;  // e

    __shared__ float2 Asd[16][66];  // duplicated A pairs
    __shared__ float  Bs[16][68];

    const int t  = threadIdx.x;
    const int tx = t & 15, ty = t >> 4;
    const int a_m = t >> 2, a_k = (t & 3) * 4;

    unsigned long long acc[4][2] = {};

    for (int k0 = 0; k0 < HW; k0 += 16) {
        float4 av = *(const float4*)&A[(size_t)(m0 + a_m) * HW + k0 + a_k];
        Asd[a_k + 0][a_m] = make_float2(av.x, av.x);
        Asd[a_k + 1][a_m] = make_float2(av.y, av.y);
        Asd[a_k + 2][a_m] = make_float2(av.z, av.z);
        Asd[a_k + 3][a_m] = make_float2(av.w, av.w);
        float4 bv = *(const float4*)&B[(size_t)(n0 + a_m) * HW + k0 + a_k];
        Bs[a_k + 0][a_m] = bv.x;
        Bs[a_k + 1][a_m] = bv.y;
        Bs[a_k + 2][a_m] = bv.z;
        Bs[a_k + 3][a_m] = bv.w;
        __syncthreads();
#pragma unroll
        for (int k = 0; k < 16; k++) {
            ulonglong2 a01 = *(const ulonglong2*)&Asd[k][ty * 4 + 0];
            ulonglong2 a23 = *(const ulonglong2*)&Asd[k][ty * 4 + 2];
            ulonglong2 bp  = *(const ulonglong2*)&Bs[k][tx * 4];
            FMA2(acc[0][0], a01.x, bp.x); FMA2(acc[0][1], a01.x, bp.y);
            FMA2(acc[1][0], a01.y, bp.x); FMA2(acc[1][1], a01.y, bp.y);
            FMA2(acc[2][0], a23.x, bp.x); FMA2(acc[2][1], a23.x, bp.y);
            FMA2(acc[3][0], a23.y, bp.x); FMA2(acc[3][1], a23.y, bp.y);
        }
        __syncthreads();
    }
    const float inv_coef = 0.047245559f;  // 1/sqrt(448)
#pragma unroll
    for (int i = 0; i < 4; i++) {
        float2 lo = *(const float2*)&acc[i][0];
        float2 hi = *(const float2*)&acc[i][1];
        float4 o = make_float4(lo.x * inv_coef, lo.y * inv_coef,
                               hi.x * inv_coef, hi.y * inv_coef);
        *(float4*)&C[(size_t)(m0 + ty * 4 + i) * D + n0 + tx * 4] = o;
    }
}

// ---------------------------------------------------------------------------
// Softmax in place over last dim (448), one warp per row. 2*16*448 rows.
// ---------------------------------------------------------------------------
__global__ void k_softmax() {
    const int warp = (blockIdx.x * blockDim.x + threadIdx.x) >> 5;
    const int lane = threadIdx.x & 31;
    if (warp >= 2 * BS * D) return;
    float* row = g_scores + (size_t)warp * D;

    float m = -1e30f;
    for (int i = lane; i < D; i += 32) m = fmaxf(m, row[i]);
#pragma unroll
    for (int off = 16; off > 0; off >>= 1) m = fmaxf(m, __shfl_xor_sync(0xffffffffu, m, off));

    float s = 0.f;
    for (int i = lane; i < D; i += 32) {
        float e = __expf(row[i] - m);
        row[i] = e;
        s += e;
    }
#pragma unroll
    for (int off = 16; off > 0; off >>= 1) s += __shfl_xor_sync(0xffffffffu, s, off);
    float inv = 1.0f / s;
    for (int i = lane; i < D; i += 32) row[i] *= inv;
}

// ---------------------------------------------------------------------------
// Apply attention (pos + neg in one pass, sharing the WvVr tile):
//   v_asta = alpha_pos @ WvVr ; v_neg = alpha_neg @ WvVr
//   out = V_s + v_asta ; Lsum += relu(v_neg - v_asta + 12)
// M=448(d) N=4096(h) K=448(e), 16 batches.
// ---------------------------------------------------------------------------
__global__ __launch_bounds__(256) void k_out(const float* __restrict__ Vs,
                                             float* __restrict__ out) {
    const int b = blockIdx.z;
    const float* A1 = g_scores + (size_t)b * D * D;
    const float* A2 = g_scores + (size_t)(BS + b) * D * D;
    const float* Bm = g_WVVR + (size_t)b * D * HW;

    const int m0 = blockIdx.y * 64;  // d
    const int n0 = blockIdx.x * 64;  // h

    __shared__ float2 Asd1[16][66];
    __shared__ float2 Asd2[16][66];
    __shared__ float  Bs[16][64];

    const int t  = threadIdx.x;
    const int tx = t & 15, ty = t >> 4;
    const int a_m = t >> 2, a_k = (t & 3) * 4;
    const int b_k = t >> 4, b_n = (t & 15) * 4;

    unsigned long long acc1[4][2] = {};
    unsigned long long acc2[4][2] = {};

    for (int k0 = 0; k0 < D; k0 += 16) {
        float4 av = *(const float4*)&A1[(size_t)(m0 + a_m) * D + k0 + a_k];
        Asd1[a_k + 0][a_m] = make_float2(av.x, av.x);
        Asd1[a_k + 1][a_m] = make_float2(av.y, av.y);
        Asd1[a_k + 2][a_m] = make_float2(av.z, av.z);
        Asd1[a_k + 3][a_m] = make_float2(av.w, av.w);
        float4 av2 = *(const float4*)&A2[(size_t)(m0 + a_m) * D + k0 + a_k];
        Asd2[a_k + 0][a_m] = make_float2(av2.x, av2.x);
        Asd2[a_k + 1][a_m] = make_float2(av2.y, av2.y);
        Asd2[a_k + 2][a_m] = make_float2(av2.z, av2.z);
        Asd2[a_k + 3][a_m] = make_float2(av2.w, av2.w);
        *(float4*)&Bs[b_k][b_n] = *(const float4*)&Bm[(size_t)(k0 + b_k) * HW + n0 + b_n];
        __syncthreads();
#pragma unroll
        for (int k = 0; k < 16; k++) {
            ulonglong2 p01 = *(const ulonglong2*)&Asd1[k][ty * 4 + 0];
            ulonglong2 p23 = *(const ulonglong2*)&Asd1[k][ty * 4 + 2];
            ulonglong2 q01 = *(const ulonglong2*)&Asd2[k][ty * 4 + 0];
            ulonglong2 q23 = *(const ulonglong2*)&Asd2[k][ty * 4 + 2];
            ulonglong2 bp  = *(const ulonglong2*)&Bs[k][tx * 4];
            FMA2(acc1[0][0], p01.x, bp.x); FMA2(acc1[0][1], p01.x, bp.y);
            FMA2(acc1[1][0], p01.y, bp.x); FMA2(acc1[1][1], p01.y, bp.y);
            FMA2(acc1[2][0], p23.x, bp.x); FMA2(acc1[2][1], p23.x, bp.y);
            FMA2(acc1[3][0], p23.y, bp.x); FMA2(acc1[3][1], p23.y, bp.y);
            FMA2(acc2[0][0], q01.x, bp.x); FMA2(acc2[0][1], q01.x, bp.y);
            FMA2(acc2[1][0], q01.y, bp.x); FMA2(acc2[1][1], q01.y, bp.y);
            FMA2(acc2[2][0], q23.x, bp.x); FMA2(acc2[2][1], q23.x, bp.y);
            FMA2(acc2[3][0], q23.y, bp.x); FMA2(acc2[3][1], q23.y, bp.y);
        }
        __syncthreads();
    }

    float lsum = 0.f;
#pragma unroll
    for (int i = 0; i < 4; i++) {
        const size_t base = ((size_t)b * D + m0 + ty * 4 + i) * HW + n0 + tx * 4;
        float2 p_lo = *(const float2*)&acc1[i][0];
        float2 p_hi = *(const float2*)&acc1[i][1];
        float2 n_lo = *(const float2*)&acc2[i][0];
        float2 n_hi = *(const float2*)&acc2[i][1];
        float4 vs = *(const float4*)&Vs[base];
        float4 o = make_float4(vs.x + p_lo.x, vs.y + p_lo.y,
                               vs.z + p_hi.x, vs.w + p_hi.y);
        *(float4*)&out[base] = o;
        lsum += fmaxf(n_lo.x - p_lo.x + 12.0f, 0.0f);
        lsum += fmaxf(n_lo.y - p_lo.y + 12.0f, 0.0f);
        lsum += fmaxf(n_hi.x - p_hi.x + 12.0f, 0.0f);
        lsum += fmaxf(n_hi.y - p_hi.y + 12.0f, 0.0f);
    }

    __shared__ float red[256];
    red[t] = lsum;
    __syncthreads();
#pragma unroll
    for (int s = 128; s > 0; s >>= 1) {
        if (t < s) red[t] += red[t + s];
        __syncthreads();
    }
    if (t == 0) atomicAdd(&g_Lsum, (double)red[0]);
}

__global__ void k_final(float* out, int out_size) {
    if (out_size > NELEM)
        out[NELEM] = (float)(g_Lsum / (double)NELEM);
}

extern "C" void kernel_launch(void* const* d_in, const int* in_sizes, int n_in,
                              void* d_out, int out_size) {
    const float* Vr = (const float*)d_in[0];
    const float* Vs = (const float*)d_in[1];
    const float* Wq = (const float*)d_in[2];
    const float* Wk = (const float*)d_in[3];
    const float* Wv = (const float*)d_in[4];
    float* out = (float*)d_out;

    k_zero<<<1, 1>>>();
    k_proj<<<dim3(HW / 64, D / 64, BS * 3), 256>>>(Vr, Vs, Wq, Wk, Wv);
    k_scores<<<dim3(D / 64, D / 64, BS * 2), 256>>>();
    {
        int warps = 2 * BS * D;
        int threads = warps * 32;
        k_softmax<<<(threads + 255) / 256, 256>>>();
    }
    k_out<<<dim3(HW / 64, D / 64, BS), 256>>>(Vs, out);
    k_final<<<1, 1>>>(out, out_size);
}

// round 4
// speedup vs baseline: 1.1036x; 1.1036x over previous
#include <cuda_runtime.h>
#include <cuda_bf16.h>

#define BS 16
#define D 448
#define HW 4096
#define NELEM (BS * D * HW)   // 29,360,128

typedef unsigned int u32;
typedef unsigned short u16;

// ---- scratch (allocation-free device globals) ----
__device__ __nv_bfloat16 g_Vr_hi[NELEM], g_Vr_lo[NELEM];
__device__ __nv_bfloat16 g_Vs_hi[NELEM], g_Vs_lo[NELEM];
__device__ __nv_bfloat16 g_W_hi[3 * D * D], g_W_lo[3 * D * D];
__device__ __nv_bfloat16 g_Q_hi[NELEM], g_Q_lo[NELEM];    // W_q @ V_s
__device__ __nv_bfloat16 g_K_hi[NELEM], g_K_lo[NELEM];    // W_k @ V_r
__device__ __nv_bfloat16 g_V2_hi[NELEM], g_V2_lo[NELEM];  // W_v @ V_r
__device__ float g_scores[2 * BS * D * D];
__device__ __nv_bfloat16 g_al_hi[2 * BS * D * D], g_al_lo[2 * BS * D * D];
__device__ double g_Lsum;

__global__ void k_zero() { g_Lsum = 0.0; }

__device__ __forceinline__ u32 pack_bf(__nv_bfloat16 a, __nv_bfloat16 b) {
    return (u32)__bfloat16_as_ushort(a) | ((u32)__bfloat16_as_ushort(b) << 16);
}

// split x = hi + lo (both bf16)
__device__ __forceinline__ void split2(float v, __nv_bfloat16& h, __nv_bfloat16& l) {
    h = __float2bfloat16(v);
    l = __float2bfloat16(v - __bfloat162float(h));
}

// ---- fragment-layout smem slot math (m16n8k16) ----
// A tile (BMx32): word slot within [atom][k16][lane][word], p = k/2
__device__ __forceinline__ int a_slot(int m, int p) {
    int atom = m >> 4, k16 = p >> 3;
    int lane = ((m & 7) << 2) | (p & 3);
    int word = ((m >> 3) & 1) | (((p >> 2) & 1) << 1);
    return ((((atom * 2 + k16) * 32 + lane) << 2) | word);
}
// B tile (32xBN): 16-bit slot within [chunk][k16][lane][word][half]
__device__ __forceinline__ int b_slot16(int n, int k) {
    int chunk = n >> 4, k16 = k >> 4;
    int lane = ((n & 7) << 2) | ((k & 7) >> 1);
    int word = (((n >> 3) & 1) << 1) | ((k >> 3) & 1);
    return (((((chunk * 2 + k16) * 32 + lane) << 2) | word) << 1) | (k & 1);
}

#define MMA(d, a, b0, b1)                                                          \
    asm volatile(                                                                  \
        "mma.sync.aligned.m16n8k16.row.col.f32.bf16.bf16.f32 "                     \
        "{%0,%1,%2,%3},{%4,%5,%6,%7},{%8,%9},{%0,%1,%2,%3};"                       \
        : "+f"(d[0]), "+f"(d[1]), "+f"(d[2]), "+f"(d[3])                           \
        : "r"(a.x), "r"(a.y), "r"(a.z), "r"(a.w), "r"(b0), "r"(b1))

// ---------------------------------------------------------------------------
__global__ void k_split_v(const float* __restrict__ Vr, const float* __restrict__ Vs) {
    int i = blockIdx.x * blockDim.x + threadIdx.x;
    int stride = gridDim.x * blockDim.x;
    for (; i < NELEM; i += stride) {
        __nv_bfloat16 h, l;
        split2(Vr[i], h, l); g_Vr_hi[i] = h; g_Vr_lo[i] = l;
        split2(Vs[i], h, l); g_Vs_hi[i] = h; g_Vs_lo[i] = l;
    }
}

__global__ void k_split_w(const float* __restrict__ Wq, const float* __restrict__ Wk,
                          const float* __restrict__ Wv) {
    int i = blockIdx.x * blockDim.x + threadIdx.x;
    if (i >= 3 * D * D) return;
    int w = i / (D * D), j = i % (D * D);
    const float* W = (w == 0) ? Wq : ((w == 1) ? Wk : Wv);
    __nv_bfloat16 h, l;
    split2(W[j], h, l);
    g_W_hi[i] = h; g_W_lo[i] = l;
}

// ---------------------------------------------------------------------------
// Projections: C[b][d][h] = W[d][c] * V[b][c][h].  BM=64 BN=128 KT=32.
// ---------------------------------------------------------------------------
__global__ __launch_bounds__(256, 1) void k_proj() {
    const int z = blockIdx.z;
    const int b = z / 3, w = z % 3;
    const __nv_bfloat16* Bhi = ((w == 0) ? g_Vs_hi : g_Vr_hi) + (size_t)b * D * HW;
    const __nv_bfloat16* Blo = ((w == 0) ? g_Vs_lo : g_Vr_lo) + (size_t)b * D * HW;
    const __nv_bfloat16* Ahi = g_W_hi + w * D * D;
    const __nv_bfloat16* Alo = g_W_lo + w * D * D;
    __nv_bfloat16* Chi = ((w == 0) ? g_Q_hi : ((w == 1) ? g_K_hi : g_V2_hi)) + (size_t)b * D * HW;
    __nv_bfloat16* Clo = ((w == 0) ? g_Q_lo : ((w == 1) ? g_K_lo : g_V2_lo)) + (size_t)b * D * HW;

    const int m0 = blockIdx.y * 64, n0 = blockIdx.x * 128;
    __shared__ u32 sA[2][1024];   // [prec][atom4][k16_2][lane][word]
    __shared__ u32 sB[2][4096];   // [prec][chunk8][k16_2][lane][word]

    const int t = threadIdx.x, wid = t >> 5, lane = t & 31;
    const int warp_m = wid & 1, warp_n = wid >> 1;

    float acc[2][4][4] = {};

    for (int k0 = 0; k0 < D; k0 += 32) {
#pragma unroll
        for (int i = 0; i < 4; i++) {  // A: 64m x 16p words
            int idx = t + 256 * i;
            int m = idx >> 4, p = idx & 15;
            int s = a_slot(m, p);
            size_t g = (size_t)(m0 + m) * D + k0 + 2 * p;
            sA[0][s] = *(const u32*)(Ahi + g);
            sA[1][s] = *(const u32*)(Alo + g);
        }
        u16* sB16h = (u16*)sB[0];
        u16* sB16l = (u16*)sB[1];
#pragma unroll
        for (int i = 0; i < 8; i++) {  // B: 32k x 64 n-pairs
            int idx = t + 256 * i;
            int k = idx >> 6, n = (idx & 63) * 2;
            size_t g = (size_t)(k0 + k) * HW + n0 + n;
            u32 vh = *(const u32*)(Bhi + g);
            u32 vl = *(const u32*)(Blo + g);
            int s0 = b_slot16(n, k), s1 = b_slot16(n + 1, k);
            sB16h[s0] = (u16)(vh & 0xffff); sB16h[s1] = (u16)(vh >> 16);
            sB16l[s0] = (u16)(vl & 0xffff); sB16l[s1] = (u16)(vl >> 16);
        }
        __syncthreads();
#pragma unroll
        for (int k16 = 0; k16 < 2; k16++) {
            uint4 Ah[2], Al[2];
#pragma unroll
            for (int ma = 0; ma < 2; ma++) {
                int at = warp_m * 2 + ma;
                int base = (at * 2 + k16) * 32 + lane;
                Ah[ma] = ((const uint4*)sA[0])[base];
                Al[ma] = ((const uint4*)sA[1])[base];
            }
#pragma unroll
            for (int ch = 0; ch < 2; ch++) {
                int cg = warp_n * 2 + ch;
                int base = (cg * 2 + k16) * 32 + lane;
                uint4 Bh = ((const uint4*)sB[0])[base];
                uint4 Bl = ((const uint4*)sB[1])[base];
#pragma unroll
                for (int ma = 0; ma < 2; ma++) {
                    MMA(acc[ma][ch * 2 + 0], Ah[ma], Bh.x, Bh.y);
                    MMA(acc[ma][ch * 2 + 0], Ah[ma], Bl.x, Bl.y);
                    MMA(acc[ma][ch * 2 + 0], Al[ma], Bh.x, Bh.y);
                    MMA(acc[ma][ch * 2 + 1], Ah[ma], Bh.z, Bh.w);
                    MMA(acc[ma][ch * 2 + 1], Ah[ma], Bl.z, Bl.w);
                    MMA(acc[ma][ch * 2 + 1], Al[ma], Bh.z, Bh.w);
                }
            }
        }
        __syncthreads();
    }

    const int r = lane >> 2, c2 = (lane & 3) * 2;
#pragma unroll
    for (int ma = 0; ma < 2; ma++)
#pragma unroll
        for (int na = 0; na < 4; na++) {
            int gm = m0 + warp_m * 32 + ma * 16 + r;
            int gn = n0 + warp_n * 32 + na * 8 + c2;
#pragma unroll
            for (int rr = 0; rr < 2; rr++) {
                float v0 = acc[ma][na][rr * 2 + 0], v1 = acc[ma][na][rr * 2 + 1];
                __nv_bfloat16 h0, l0, h1, l1;
                split2(v0, h0, l0);
                split2(v1, h1, l1);
                size_t g = (size_t)(gm + rr * 8) * HW + gn;
                *(u32*)(Chi + g) = pack_bf(h0, h1);
                *(u32*)(Clo + g) = pack_bf(l0, l1);
            }
        }
}

// ---------------------------------------------------------------------------
// Scores (NT): scores[neg][b][d][e] = (1/sqrt(D)) * Q[b,d,:] . K[b',e,:]
// BM=64 BN=64 KT=32, K=4096.  Warp tile 32x16.
// ---------------------------------------------------------------------------
__global__ __launch_bounds__(256, 1) void k_scores() {
    const int z = blockIdx.z;
    const int b = z >> 1, neg = z & 1;
    const int bk = neg ? ((b + 1) & (BS - 1)) : b;
    const __nv_bfloat16* Ahi = g_Q_hi + (size_t)b * D * HW;
    const __nv_bfloat16* Alo = g_Q_lo + (size_t)b * D * HW;
    const __nv_bfloat16* Bhi = g_K_hi + (size_t)bk * D * HW;
    const __nv_bfloat16* Blo = g_K_lo + (size_t)bk * D * HW;
    float* C = g_scores + ((size_t)neg * BS + b) * D * D;

    const int m0 = blockIdx.y * 64, n0 = blockIdx.x * 64;
    __shared__ u32 sA[2][1024];  // atoms 4
    __shared__ u32 sB[2][1024];  // chunks 4

    const int t = threadIdx.x, wid = t >> 5, lane = t & 31;
    const int warp_m = wid & 1, warp_n = wid >> 1;

    float acc[2][2][4] = {};

    for (int k0 = 0; k0 < HW; k0 += 32) {
#pragma unroll
        for (int i = 0; i < 4; i++) {
            int idx = t + 256 * i;
            int m = idx >> 4, p = idx & 15;
            int s = a_slot(m, p);
            size_t g = (size_t)(m0 + m) * HW + k0 + 2 * p;
            sA[0][s] = *(const u32*)(Ahi + g);
            sA[1][s] = *(const u32*)(Alo + g);
        }
#pragma unroll
        for (int i = 0; i < 4; i++) {
            int idx = t + 256 * i;
            int n = idx >> 4, p = idx & 15;
            int s = b_slot16(n, 2 * p) >> 1;  // word index (both halves same word)
            size_t g = (size_t)(n0 + n) * HW + k0 + 2 * p;
            sB[0][s] = *(const u32*)(Bhi + g);
            sB[1][s] = *(const u32*)(Blo + g);
        }
        __syncthreads();
#pragma unroll
        for (int k16 = 0; k16 < 2; k16++) {
            uint4 Ah[2], Al[2];
#pragma unroll
            for (int ma = 0; ma < 2; ma++) {
                int at = warp_m * 2 + ma;
                int base = (at * 2 + k16) * 32 + lane;
                Ah[ma] = ((const uint4*)sA[0])[base];
                Al[ma] = ((const uint4*)sA[1])[base];
            }
            int base = (warp_n * 2 + k16) * 32 + lane;
            uint4 Bh = ((const uint4*)sB[0])[base];
            uint4 Bl = ((const uint4*)sB[1])[base];
#pragma unroll
            for (int ma = 0; ma < 2; ma++) {
                MMA(acc[ma][0], Ah[ma], Bh.x, Bh.y);
                MMA(acc[ma][0], Ah[ma], Bl.x, Bl.y);
                MMA(acc[ma][0], Al[ma], Bh.x, Bh.y);
                MMA(acc[ma][1], Ah[ma], Bh.z, Bh.w);
                MMA(acc[ma][1], Ah[ma], Bl.z, Bl.w);
                MMA(acc[ma][1], Al[ma], Bh.z, Bh.w);
            }
        }
        __syncthreads();
    }

    const float inv_coef = 0.047245559f;  // 1/sqrt(448)
    const int r = lane >> 2, c2 = (lane & 3) * 2;
#pragma unroll
    for (int ma = 0; ma < 2; ma++)
#pragma unroll
        for (int na = 0; na < 2; na++) {
            int gm = m0 + warp_m * 32 + ma * 16 + r;
            int gn = n0 + warp_n * 16 + na * 8 + c2;
#pragma unroll
            for (int rr = 0; rr < 2; rr++) {
                float2 o = make_float2(acc[ma][na][rr * 2 + 0] * inv_coef,
                                       acc[ma][na][rr * 2 + 1] * inv_coef);
                *(float2*)(C + (size_t)(gm + rr * 8) * D + gn) = o;
            }
        }
}

// ---------------------------------------------------------------------------
// Softmax over 448 + split alpha to bf16 hi/lo. One warp per row.
// ---------------------------------------------------------------------------
__global__ void k_softmax() {
    const int warp = (blockIdx.x * blockDim.x + threadIdx.x) >> 5;
    const int lane = threadIdx.x & 31;
    if (warp >= 2 * BS * D) return;
    const float* row = g_scores + (size_t)warp * D;
    __nv_bfloat16* oh = g_al_hi + (size_t)warp * D;
    __nv_bfloat16* ol = g_al_lo + (size_t)warp * D;

    float m = -1e30f;
    for (int i = lane; i < D; i += 32) m = fmaxf(m, row[i]);
#pragma unroll
    for (int off = 16; off > 0; off >>= 1) m = fmaxf(m, __shfl_xor_sync(0xffffffffu, m, off));

    float s = 0.f;
    float e[14];
#pragma unroll
    for (int j = 0; j < 14; j++) {
        e[j] = __expf(row[lane + 32 * j] - m);
        s += e[j];
    }
#pragma unroll
    for (int off = 16; off > 0; off >>= 1) s += __shfl_xor_sync(0xffffffffu, s, off);
    float inv = 1.0f / s;
#pragma unroll
    for (int j = 0; j < 14; j++) {
        __nv_bfloat16 h, l;
        split2(e[j] * inv, h, l);
        oh[lane + 32 * j] = h;
        ol[lane + 32 * j] = l;
    }
}

// ---------------------------------------------------------------------------
// Output: v_asta = alpha_pos @ WvVr ; v_neg = alpha_neg @ WvVr
//   out = V_s + v_asta ; Lsum += relu(v_neg - v_asta + 12)
// BM=64 BN=128 KT=32, K=448.
// ---------------------------------------------------------------------------
__global__ __launch_bounds__(256, 1) void k_out(const float* __restrict__ Vs,
                                                float* __restrict__ out) {
    const int b = blockIdx.z;
    const size_t poff = (size_t)b * D * D;
    const size_t noff = (size_t)(BS + b) * D * D;
    const __nv_bfloat16* Bhi = g_V2_hi + (size_t)b * D * HW;
    const __nv_bfloat16* Blo = g_V2_lo + (size_t)b * D * HW;

    const int m0 = blockIdx.y * 64, n0 = blockIdx.x * 128;
    __shared__ u32 sA1[2][1024];
    __shared__ u32 sA2[2][1024];
    __shared__ u32 sB[2][4096];

    const int t = threadIdx.x, wid = t >> 5, lane = t & 31;
    const int warp_m = wid & 1, warp_n = wid >> 1;

    float acc1[2][4][4] = {};
    float acc2[2][4][4] = {};

    for (int k0 = 0; k0 < D; k0 += 32) {
#pragma unroll
        for (int i = 0; i < 4; i++) {
            int idx = t + 256 * i;
            int m = idx >> 4, p = idx & 15;
            int s = a_slot(m, p);
            size_t g = (size_t)(m0 + m) * D + k0 + 2 * p;
            sA1[0][s] = *(const u32*)(g_al_hi + poff + g);
            sA1[1][s] = *(const u32*)(g_al_lo + poff + g);
            sA2[0][s] = *(const u32*)(g_al_hi + noff + g);
            sA2[1][s] = *(const u32*)(g_al_lo + noff + g);
        }
        u16* sB16h = (u16*)sB[0];
        u16* sB16l = (u16*)sB[1];
#pragma unroll
        for (int i = 0; i < 8; i++) {
            int idx = t + 256 * i;
            int k = idx >> 6, n = (idx & 63) * 2;
            size_t g = (size_t)(k0 + k) * HW + n0 + n;
            u32 vh = *(const u32*)(Bhi + g);
            u32 vl = *(const u32*)(Blo + g);
            int s0 = b_slot16(n, k), s1 = b_slot16(n + 1, k);
            sB16h[s0] = (u16)(vh & 0xffff); sB16h[s1] = (u16)(vh >> 16);
            sB16l[s0] = (u16)(vl & 0xffff); sB16l[s1] = (u16)(vl >> 16);
        }
        __syncthreads();
#pragma unroll
        for (int k16 = 0; k16 < 2; k16++) {
            uint4 P1h[2], P1l[2], P2h[2], P2l[2];
#pragma unroll
            for (int ma = 0; ma < 2; ma++) {
                int at = warp_m * 2 + ma;
                int base = (at * 2 + k16) * 32 + lane;
                P1h[ma] = ((const uint4*)sA1[0])[base];
                P1l[ma] = ((const uint4*)sA1[1])[base];
                P2h[ma] = ((const uint4*)sA2[0])[base];
                P2l[ma] = ((const uint4*)sA2[1])[base];
            }
#pragma unroll
            for (int ch = 0; ch < 2; ch++) {
                int cg = warp_n * 2 + ch;
                int base = (cg * 2 + k16) * 32 + lane;
                uint4 Bh = ((const uint4*)sB[0])[base];
                uint4 Bl = ((const uint4*)sB[1])[base];
#pragma unroll
                for (int ma = 0; ma < 2; ma++) {
                    MMA(acc1[ma][ch * 2 + 0], P1h[ma], Bh.x, Bh.y);
                    MMA(acc1[ma][ch * 2 + 0], P1h[ma], Bl.x, Bl.y);
                    MMA(acc1[ma][ch * 2 + 0], P1l[ma], Bh.x, Bh.y);
                    MMA(acc1[ma][ch * 2 + 1], P1h[ma], Bh.z, Bh.w);
                    MMA(acc1[ma][ch * 2 + 1], P1h[ma], Bl.z, Bl.w);
                    MMA(acc1[ma][ch * 2 + 1], P1l[ma], Bh.z, Bh.w);
                    MMA(acc2[ma][ch * 2 + 0], P2h[ma], Bh.x, Bh.y);
                    MMA(acc2[ma][ch * 2 + 0], P2h[ma], Bl.x, Bl.y);
                    MMA(acc2[ma][ch * 2 + 0], P2l[ma], Bh.x, Bh.y);
                    MMA(acc2[ma][ch * 2 + 1], P2h[ma], Bh.z, Bh.w);
                    MMA(acc2[ma][ch * 2 + 1], P2h[ma], Bl.z, Bl.w);
                    MMA(acc2[ma][ch * 2 + 1], P2l[ma], Bh.z, Bh.w);
                }
            }
        }
        __syncthreads();
    }

    float lsum = 0.f;
    const int r = lane >> 2, c2 = (lane & 3) * 2;
#pragma unroll
    for (int ma = 0; ma < 2; ma++)
#pragma unroll
        for (int na = 0; na < 4; na++) {
            int gm = m0 + warp_m * 32 + ma * 16 + r;
            int gn = n0 + warp_n * 32 + na * 8 + c2;
#pragma unroll
            for (int rr = 0; rr < 2; rr++) {
                float p0 = acc1[ma][na][rr * 2 + 0], p1 = acc1[ma][na][rr * 2 + 1];
                float q0 = acc2[ma][na][rr * 2 + 0], q1 = acc2[ma][na][rr * 2 + 1];
                size_t g = ((size_t)b * D + gm + rr * 8) * HW + gn;
                float2 vs = *(const float2*)(Vs + g);
                *(float2*)(out + g) = make_float2(vs.x + p0, vs.y + p1);
                lsum += fmaxf(q0 - p0 + 12.0f, 0.0f);
                lsum += fmaxf(q1 - p1 + 12.0f, 0.0f);
            }
        }

    __syncthreads();
    float* red = (float*)sB[0];
    red[t] = lsum;
    __syncthreads();
#pragma unroll
    for (int s = 128; s > 0; s >>= 1) {
        if (t < s) red[t] += red[t + s];
        __syncthreads();
    }
    if (t == 0) atomicAdd(&g_Lsum, (double)red[0]);
}

__global__ void k_final(float* out, int out_size) {
    if (out_size > NELEM)
        out[NELEM] = (float)(g_Lsum / (double)NELEM);
}

extern "C" void kernel_launch(void* const* d_in, const int* in_sizes, int n_in,
                              void* d_out, int out_size) {
    const float* Vr = (const float*)d_in[0];
    const float* Vs = (const float*)d_in[1];
    const float* Wq = (const float*)d_in[2];
    const float* Wk = (const float*)d_in[3];
    const float* Wv = (const float*)d_in[4];
    float* out = (float*)d_out;

    k_zero<<<1, 1>>>();
    k_split_v<<<14336, 256>>>(Vr, Vs);
    k_split_w<<<(3 * D * D + 255) / 256, 256>>>(Wq, Wk, Wv);
    k_proj<<<dim3(HW / 128, D / 64, BS * 3), 256>>>();
    k_scores<<<dim3(D / 64, D / 64, BS * 2), 256>>>();
    k_softmax<<<(2 * BS * D * 32 + 255) / 256, 256>>>();
    k_out<<<dim3(HW / 128, D / 64, BS), 256>>>(Vs, out);
    k_final<<<1, 1>>>(out, out_size);
}

// round 6
// speedup vs baseline: 1.9735x; 1.7882x over previous
#include <cuda_runtime.h>
#include <cuda_bf16.h>

#define BS 16
#define D 448
#define HW 4096
#define NELEM (BS * D * HW)

typedef unsigned int u32;

// ---- scratch ----
__device__ __nv_bfloat16 g_Vr_hi[NELEM], g_Vr_lo[NELEM];
__device__ __nv_bfloat16 g_Vs_hi[NELEM], g_Vs_lo[NELEM];
__device__ __nv_bfloat16 g_W_hi[3 * D * D], g_W_lo[3 * D * D];
__device__ __nv_bfloat16 g_Q_hi[NELEM], g_Q_lo[NELEM];
__device__ __nv_bfloat16 g_K_hi[NELEM], g_K_lo[NELEM];
__device__ __nv_bfloat16 g_V2_hi[NELEM], g_V2_lo[NELEM];
__device__ float g_scores[2 * BS * D * D];
__device__ __nv_bfloat16 g_al_hi[2 * BS * D * D], g_al_lo[2 * BS * D * D];
__device__ double g_Lsum;

__global__ void k_zero() { g_Lsum = 0.0; }

__device__ __forceinline__ u32 smem_u32(const void* p) {
    u32 a;
    asm("{ .reg .u64 t; cvta.to.shared.u64 t, %1; cvt.u32.u64 %0, t; }" : "=r"(a) : "l"(p));
    return a;
}

#define LDSM4(r0, r1, r2, r3, a)                                              \
    asm volatile("ldmatrix.sync.aligned.m8n8.x4.shared.b16 {%0,%1,%2,%3},[%4];" \
                 : "=r"(r0), "=r"(r1), "=r"(r2), "=r"(r3) : "r"(a))
#define LDSM4T(r0, r1, r2, r3, a)                                             \
    asm volatile("ldmatrix.sync.aligned.m8n8.x4.trans.shared.b16 {%0,%1,%2,%3},[%4];" \
                 : "=r"(r0), "=r"(r1), "=r"(r2), "=r"(r3) : "r"(a))
#define MMA(d, a0, a1, a2, a3, b0, b1)                                        \
    asm volatile(                                                             \
        "mma.sync.aligned.m16n8k16.row.col.f32.bf16.bf16.f32 "                \
        "{%0,%1,%2,%3},{%4,%5,%6,%7},{%8,%9},{%0,%1,%2,%3};"                  \
        : "+f"(d[0]), "+f"(d[1]), "+f"(d[2]), "+f"(d[3])                      \
        : "r"(a0), "r"(a1), "r"(a2), "r"(a3), "r"(b0), "r"(b1))

__device__ __forceinline__ void split2(float v, __nv_bfloat16& h, __nv_bfloat16& l) {
    h = __float2bfloat16(v);
    l = __float2bfloat16(v - __bfloat162float(h));
}
__device__ __forceinline__ u32 pack_bf(__nv_bfloat16 a, __nv_bfloat16 b) {
    return (u32)__bfloat16_as_ushort(a) | ((u32)__bfloat16_as_ushort(b) << 16);
}

__global__ void k_split_v(const float* __restrict__ Vr, const float* __restrict__ Vs) {
    int i = blockIdx.x * blockDim.x + threadIdx.x;
    int stride = gridDim.x * blockDim.x;
    for (; i < NELEM; i += stride) {
        __nv_bfloat16 h, l;
        split2(Vr[i], h, l); g_Vr_hi[i] = h; g_Vr_lo[i] = l;
        split2(Vs[i], h, l); g_Vs_hi[i] = h; g_Vs_lo[i] = l;
    }
}
__global__ void k_split_w(const float* __restrict__ Wq, const float* __restrict__ Wk,
                          const float* __restrict__ Wv) {
    int i = blockIdx.x * blockDim.x + threadIdx.x;
    if (i >= 3 * D * D) return;
    int w = i / (D * D), j = i % (D * D);
    const float* W = (w == 0) ? Wq : ((w == 1) ? Wk : Wv);
    __nv_bfloat16 h, l;
    split2(W[j], h, l);
    g_W_hi[i] = h; g_W_lo[i] = l;
}

// pitches (bytes)
#define PA 80     // A tiles: 128 rows x 32 halves (64B) + 16B pad
#define PBT 144   // trans-B tiles: 32 rows x 64 halves (128B) + 16B pad

// =========================================================================
// k_scores: M=128(d) N=64(e) K=4096. A=Q[m][k], B=K[n][k], both K-major.
// 8 warps: warp_m = wid&3 (32 rows), warp_n = wid>>2 (32 cols).
// =========================================================================
#define SCR_AH 0
#define SCR_AL 10240
#define SCR_BH 20480
#define SCR_BL 25600
#define SCR_SMEM 30720

__global__ __launch_bounds__(256, 2) void k_scores() {
    extern __shared__ char sm[];
    const u32 sb = smem_u32(sm);
    const int t = threadIdx.x, wid = t >> 5, l = t & 31;
    const int warp_m = wid & 3, warp_n = wid >> 2;

    const int z = blockIdx.z, b = z >> 1, neg = z & 1;
    const int bk = neg ? ((b + 1) & (BS - 1)) : b;
    const __nv_bfloat16* Ahi = g_Q_hi + (size_t)b * D * HW;
    const __nv_bfloat16* Alo = g_Q_lo + (size_t)b * D * HW;
    const __nv_bfloat16* Bhi = g_K_hi + (size_t)bk * D * HW;
    const __nv_bfloat16* Blo = g_K_lo + (size_t)bk * D * HW;
    float* C = g_scores + ((size_t)neg * BS + b) * D * D;

    const int m0 = blockIdx.y * 128, n0 = blockIdx.x * 64;

    // lane-derived ldmatrix addresses (byte offsets, without k16 term)
    const u32 aRow = warp_m * 32 + (l & 15);
    const u32 aCol = (l >> 4) * 16;  // bytes
    const u32 bRow = ((l >> 4) & 1) * 8 + (l & 7);
    const u32 bCol = ((l >> 3) & 1) * 16;

    float acc[2][4][4] = {};

    for (int k0 = 0; k0 < HW; k0 += 32) {
        // load A: 2 x (idx: m = idx&127, c = idx>>7)
#pragma unroll
        for (int i = 0; i < 2; i++) {
            int idx = t + 256 * i;
            int m = idx & 127, c = idx >> 7;
            int gm = m0 + m; if (gm > 447) gm = 447;
            const size_t g = (size_t)gm * HW + k0 + c * 8;
            *(uint4*)(sm + SCR_AH + m * PA + c * 16) = *(const uint4*)(Ahi + g);
            *(uint4*)(sm + SCR_AL + m * PA + c * 16) = *(const uint4*)(Alo + g);
        }
        {
            int n = t >> 2, c = t & 3;
            const size_t g = (size_t)(n0 + n) * HW + k0 + c * 8;
            *(uint4*)(sm + SCR_BH + n * PA + c * 16) = *(const uint4*)(Bhi + g);
            *(uint4*)(sm + SCR_BL + n * PA + c * 16) = *(const uint4*)(Blo + g);
        }
        __syncthreads();
#pragma unroll
        for (int k16 = 0; k16 < 2; k16++) {
            const u32 kb = k16 * 32;  // 16 halves
            u32 ah[2][4], al[2][4];
#pragma unroll
            for (int ma = 0; ma < 2; ma++) {
                u32 off = (aRow + ma * 16) * PA + aCol + kb;
                LDSM4(ah[ma][0], ah[ma][1], ah[ma][2], ah[ma][3], sb + SCR_AH + off);
                LDSM4(al[ma][0], al[ma][1], al[ma][2], al[ma][3], sb + SCR_AL + off);
            }
            u32 bh[8], bl[8];
#pragma unroll
            for (int p = 0; p < 2; p++) {
                u32 off = (warp_n * 32 + p * 16 + bRow) * PA + bCol + kb;
                LDSM4(bh[p * 4 + 0], bh[p * 4 + 1], bh[p * 4 + 2], bh[p * 4 + 3], sb + SCR_BH + off);
                LDSM4(bl[p * 4 + 0], bl[p * 4 + 1], bl[p * 4 + 2], bl[p * 4 + 3], sb + SCR_BL + off);
            }
#pragma unroll
            for (int ma = 0; ma < 2; ma++)
#pragma unroll
                for (int na = 0; na < 4; na++) {
                    float* d = acc[ma][na];
                    u32 h0 = bh[na * 2], h1 = bh[na * 2 + 1];
                    u32 l0 = bl[na * 2], l1 = bl[na * 2 + 1];
                    MMA(d, ah[ma][0], ah[ma][1], ah[ma][2], ah[ma][3], h0, h1);
                    MMA(d, ah[ma][0], ah[ma][1], ah[ma][2], ah[ma][3], l0, l1);
                    MMA(d, al[ma][0], al[ma][1], al[ma][2], al[ma][3], h0, h1);
                }
        }
        __syncthreads();
    }

    const float inv_coef = 0.047245559f;
    const int r = l >> 2, c2 = (l & 3) * 2;
#pragma unroll
    for (int ma = 0; ma < 2; ma++)
#pragma unroll
        for (int na = 0; na < 4; na++)
#pragma unroll
            for (int rr = 0; rr < 2; rr++) {
                int gm = m0 + warp_m * 32 + ma * 16 + rr * 8 + r;
                if (gm < 448) {
                    int gn = n0 + warp_n * 32 + na * 8 + c2;
                    float2 o = make_float2(acc[ma][na][rr * 2] * inv_coef,
                                           acc[ma][na][rr * 2 + 1] * inv_coef);
                    *(float2*)(C + (size_t)gm * D + gn) = o;
                }
            }
}

// =========================================================================
// k_proj: M=128(d) N=64(h) K=448(c). A=W K-major, B=V [c][h] n-major (trans).
// =========================================================================
#define PRJ_AH 0
#define PRJ_AL 10240
#define PRJ_BH 20480
#define PRJ_BL 25088
#define PRJ_SMEM 29696

__global__ __launch_bounds__(256, 2) void k_proj() {
    extern __shared__ char sm[];
    const u32 sb = smem_u32(sm);
    const int t = threadIdx.x, wid = t >> 5, l = t & 31;
    const int warp_m = wid & 3, warp_n = wid >> 2;

    const int z = blockIdx.z, b = z / 3, w = z % 3;
    const __nv_bfloat16* Ahi = g_W_hi + w * D * D;
    const __nv_bfloat16* Alo = g_W_lo + w * D * D;
    const __nv_bfloat16* Bhi = ((w == 0) ? g_Vs_hi : g_Vr_hi) + (size_t)b * D * HW;
    const __nv_bfloat16* Blo = ((w == 0) ? g_Vs_lo : g_Vr_lo) + (size_t)b * D * HW;
    __nv_bfloat16* Chi = ((w == 0) ? g_Q_hi : ((w == 1) ? g_K_hi : g_V2_hi)) + (size_t)b * D * HW;
    __nv_bfloat16* Clo = ((w == 0) ? g_Q_lo : ((w == 1) ? g_K_lo : g_V2_lo)) + (size_t)b * D * HW;

    const int m0 = blockIdx.y * 128, n0 = blockIdx.x * 64;

    const u32 aRow = warp_m * 32 + (l & 15);
    const u32 aCol = (l >> 4) * 16;
    const u32 btRow = (l & 15);            // k within k16 block
    const u32 btCol = (l >> 4) * 16;       // n sub-block bytes

    float acc[2][4][4] = {};

    for (int k0 = 0; k0 < D; k0 += 32) {
#pragma unroll
        for (int i = 0; i < 2; i++) {
            int idx = t + 256 * i;
            int m = idx & 127, c = idx >> 7;
            int gm = m0 + m; if (gm > 447) gm = 447;
            const size_t g = (size_t)gm * D + k0 + c * 8;
            *(uint4*)(sm + PRJ_AH + m * PA + c * 16) = *(const uint4*)(Ahi + g);
            *(uint4*)(sm + PRJ_AL + m * PA + c * 16) = *(const uint4*)(Alo + g);
        }
        {
            int r = t >> 3, c = t & 7;
            const size_t g = (size_t)(k0 + r) * HW + n0 + c * 8;
            *(uint4*)(sm + PRJ_BH + r * PBT + c * 16) = *(const uint4*)(Bhi + g);
            *(uint4*)(sm + PRJ_BL + r * PBT + c * 16) = *(const uint4*)(Blo + g);
        }
        __syncthreads();
#pragma unroll
        for (int k16 = 0; k16 < 2; k16++) {
            u32 ah[2][4], al[2][4];
#pragma unroll
            for (int ma = 0; ma < 2; ma++) {
                u32 off = (aRow + ma * 16) * PA + aCol + k16 * 32;
                LDSM4(ah[ma][0], ah[ma][1], ah[ma][2], ah[ma][3], sb + PRJ_AH + off);
                LDSM4(al[ma][0], al[ma][1], al[ma][2], al[ma][3], sb + PRJ_AL + off);
            }
            u32 bh[8], bl[8];
#pragma unroll
            for (int p = 0; p < 2; p++) {
                u32 off = (k16 * 16 + btRow) * PBT + (warp_n * 32 + p * 16) * 2 + btCol;
                LDSM4T(bh[p * 4 + 0], bh[p * 4 + 1], bh[p * 4 + 2], bh[p * 4 + 3], sb + PRJ_BH + off);
                LDSM4T(bl[p * 4 + 0], bl[p * 4 + 1], bl[p * 4 + 2], bl[p * 4 + 3], sb + PRJ_BL + off);
            }
#pragma unroll
            for (int ma = 0; ma < 2; ma++)
#pragma unroll
                for (int na = 0; na < 4; na++) {
                    float* d = acc[ma][na];
                    u32 h0 = bh[na * 2], h1 = bh[na * 2 + 1];
                    u32 l0 = bl[na * 2], l1 = bl[na * 2 + 1];
                    MMA(d, ah[ma][0], ah[ma][1], ah[ma][2], ah[ma][3], h0, h1);
                    MMA(d, ah[ma][0], ah[ma][1], ah[ma][2], ah[ma][3], l0, l1);
                    MMA(d, al[ma][0], al[ma][1], al[ma][2], al[ma][3], h0, h1);
                }
        }
        __syncthreads();
    }

    const int r = l >> 2, c2 = (l & 3) * 2;
#pragma unroll
    for (int ma = 0; ma < 2; ma++)
#pragma unroll
        for (int na = 0; na < 4; na++)
#pragma unroll
            for (int rr = 0; rr < 2; rr++) {
                int gm = m0 + warp_m * 32 + ma * 16 + rr * 8 + r;
                if (gm < 448) {
                    int gn = n0 + warp_n * 32 + na * 8 + c2;
                    float v0 = acc[ma][na][rr * 2], v1 = acc[ma][na][rr * 2 + 1];
                    __nv_bfloat16 h0, l0_, h1, l1_;
                    split2(v0, h0, l0_);
                    split2(v1, h1, l1_);
                    size_t g = (size_t)gm * HW + gn;
                    *(u32*)(Chi + g) = pack_bf(h0, h1);
                    *(u32*)(Clo + g) = pack_bf(l0_, l1_);
                }
            }
}

// ---------------- softmax + split alpha ----------------
__global__ void k_softmax() {
    const int warp = (blockIdx.x * blockDim.x + threadIdx.x) >> 5;
    const int lane = threadIdx.x & 31;
    if (warp >= 2 * BS * D) return;
    const float* row = g_scores + (size_t)warp * D;
    __nv_bfloat16* oh = g_al_hi + (size_t)warp * D;
    __nv_bfloat16* ol = g_al_lo + (size_t)warp * D;

    float m = -1e30f;
    for (int i = lane; i < D; i += 32) m = fmaxf(m, row[i]);
#pragma unroll
    for (int off = 16; off > 0; off >>= 1) m = fmaxf(m, __shfl_xor_sync(0xffffffffu, m, off));
    float s = 0.f;
    float e[14];
#pragma unroll
    for (int j = 0; j < 14; j++) { e[j] = __expf(row[lane + 32 * j] - m); s += e[j]; }
#pragma unroll
    for (int off = 16; off > 0; off >>= 1) s += __shfl_xor_sync(0xffffffffu, s, off);
    float inv = 1.0f / s;
#pragma unroll
    for (int j = 0; j < 14; j++) {
        __nv_bfloat16 h, l;
        split2(e[j] * inv, h, l);
        oh[lane + 32 * j] = h;
        ol[lane + 32 * j] = l;
    }
}

// =========================================================================
// k_out: M=128(d) N=64(h) K=448(e). Dual A (pos/neg) sharing trans-B tiles.
// =========================================================================
#define OUT_P_H 0
#define OUT_P_L 10240
#define OUT_N_H 20480
#define OUT_N_L 30720
#define OUT_BH 40960
#define OUT_BL 45568
#define OUT_SMEM 50176

__global__ __launch_bounds__(256) void k_out(const float* __restrict__ Vs,
                                             float* __restrict__ out) {
    extern __shared__ char sm[];
    const u32 sb = smem_u32(sm);
    const int t = threadIdx.x, wid = t >> 5, l = t & 31;
    const int warp_m = wid & 3, warp_n = wid >> 2;

    const int b = blockIdx.z;
    const __nv_bfloat16* A1h = g_al_hi + (size_t)b * D * D;
    const __nv_bfloat16* A1l = g_al_lo + (size_t)b * D * D;
    const __nv_bfloat16* A2h = g_al_hi + (size_t)(BS + b) * D * D;
    const __nv_bfloat16* A2l = g_al_lo + (size_t)(BS + b) * D * D;
    const __nv_bfloat16* Bhi = g_V2_hi + (size_t)b * D * HW;
    const __nv_bfloat16* Blo = g_V2_lo + (size_t)b * D * HW;

    const int m0 = blockIdx.y * 128, n0 = blockIdx.x * 64;

    const u32 aRow = warp_m * 32 + (l & 15);
    const u32 aCol = (l >> 4) * 16;
    const u32 btRow = (l & 15);
    const u32 btCol = (l >> 4) * 16;

    float accP[2][4][4] = {};
    float accN[2][4][4] = {};

    for (int k0 = 0; k0 < D; k0 += 32) {
#pragma unroll
        for (int i = 0; i < 2; i++) {
            int idx = t + 256 * i;
            int m = idx & 127, c = idx >> 7;
            int gm = m0 + m; if (gm > 447) gm = 447;
            const size_t g = (size_t)gm * D + k0 + c * 8;
            *(uint4*)(sm + OUT_P_H + m * PA + c * 16) = *(const uint4*)(A1h + g);
            *(uint4*)(sm + OUT_P_L + m * PA + c * 16) = *(const uint4*)(A1l + g);
            *(uint4*)(sm + OUT_N_H + m * PA + c * 16) = *(const uint4*)(A2h + g);
            *(uint4*)(sm + OUT_N_L + m * PA + c * 16) = *(const uint4*)(A2l + g);
        }
        {
            int r = t >> 3, c = t & 7;
            const size_t g = (size_t)(k0 + r) * HW + n0 + c * 8;
            *(uint4*)(sm + OUT_BH + r * PBT + c * 16) = *(const uint4*)(Bhi + g);
            *(uint4*)(sm + OUT_BL + r * PBT + c * 16) = *(const uint4*)(Blo + g);
        }
        __syncthreads();
#pragma unroll
        for (int k16 = 0; k16 < 2; k16++) {
            u32 bh[8], bl[8];
#pragma unroll
            for (int p = 0; p < 2; p++) {
                u32 off = (k16 * 16 + btRow) * PBT + (warp_n * 32 + p * 16) * 2 + btCol;
                LDSM4T(bh[p * 4 + 0], bh[p * 4 + 1], bh[p * 4 + 2], bh[p * 4 + 3], sb + OUT_BH + off);
                LDSM4T(bl[p * 4 + 0], bl[p * 4 + 1], bl[p * 4 + 2], bl[p * 4 + 3], sb + OUT_BL + off);
            }
#pragma unroll
            for (int ma = 0; ma < 2; ma++) {
                u32 off = (aRow + ma * 16) * PA + aCol + k16 * 32;
                u32 ph[4], pl[4], nh[4], nl[4];
                LDSM4(ph[0], ph[1], ph[2], ph[3], sb + OUT_P_H + off);
                LDSM4(pl[0], pl[1], pl[2], pl[3], sb + OUT_P_L + off);
                LDSM4(nh[0], nh[1], nh[2], nh[3], sb + OUT_N_H + off);
                LDSM4(nl[0], nl[1], nl[2], nl[3], sb + OUT_N_L + off);
#pragma unroll
                for (int na = 0; na < 4; na++) {
                    u32 h0 = bh[na * 2], h1 = bh[na * 2 + 1];
                    u32 l0 = bl[na * 2], l1 = bl[na * 2 + 1];
                    float* dp = accP[ma][na];
                    float* dn = accN[ma][na];
                    MMA(dp, ph[0], ph[1], ph[2], ph[3], h0, h1);
                    MMA(dp, ph[0], ph[1], ph[2], ph[3], l0, l1);
                    MMA(dp, pl[0], pl[1], pl[2], pl[3], h0, h1);
                    MMA(dn, nh[0], nh[1], nh[2], nh[3], h0, h1);
                    MMA(dn, nh[0], nh[1], nh[2], nh[3], l0, l1);
                    MMA(dn, nl[0], nl[1], nl[2], nl[3], h0, h1);
                }
            }
        }
        __syncthreads();
    }

    float lsum = 0.f;
    const int r = l >> 2, c2 = (l & 3) * 2;
#pragma unroll
    for (int ma = 0; ma < 2; ma++)
#pragma unroll
        for (int na = 0; na < 4; na++)
#pragma unroll
            for (int rr = 0; rr < 2; rr++) {
                int gm = m0 + warp_m * 32 + ma * 16 + rr * 8 + r;
                if (gm < 448) {
                    int gn = n0 + warp_n * 32 + na * 8 + c2;
                    float p0 = accP[ma][na][rr * 2], p1 = accP[ma][na][rr * 2 + 1];
                    float q0 = accN[ma][na][rr * 2], q1 = accN[ma][na][rr * 2 + 1];
                    size_t g = ((size_t)b * D + gm) * HW + gn;
                    float2 vs = *(const float2*)(Vs + g);
                    *(float2*)(out + g) = make_float2(vs.x + p0, vs.y + p1);
                    lsum += fmaxf(q0 - p0 + 12.0f, 0.0f);
                    lsum += fmaxf(q1 - p1 + 12.0f, 0.0f);
                }
            }

    __syncthreads();
    float* red = (float*)sm;
    red[t] = lsum;
    __syncthreads();
#pragma unroll
    for (int s = 128; s > 0; s >>= 1) {
        if (t < s) red[t] += red[t + s];
        __syncthreads();
    }
    if (t == 0) atomicAdd(&g_Lsum, (double)red[0]);
}

__global__ void k_final(float* out, int out_size) {
    if (out_size > NELEM)
        out[NELEM] = (float)(g_Lsum / (double)NELEM);
}

extern "C" void kernel_launch(void* const* d_in, const int* in_sizes, int n_in,
                              void* d_out, int out_size) {
    const float* Vr = (const float*)d_in[0];
    const float* Vs = (const float*)d_in[1];
    const float* Wq = (const float*)d_in[2];
    const float* Wk = (const float*)d_in[3];
    const float* Wv = (const float*)d_in[4];
    float* out = (float*)d_out;

    cudaFuncSetAttribute(k_proj, cudaFuncAttributeMaxDynamicSharedMemorySize, PRJ_SMEM);
    cudaFuncSetAttribute(k_scores, cudaFuncAttributeMaxDynamicSharedMemorySize, SCR_SMEM);
    cudaFuncSetAttribute(k_out, cudaFuncAttributeMaxDynamicSharedMemorySize, OUT_SMEM);

    k_zero<<<1, 1>>>();
    k_split_v<<<14336, 256>>>(Vr, Vs);
    k_split_w<<<(3 * D * D + 255) / 256, 256>>>(Wq, Wk, Wv);
    k_proj<<<dim3(HW / 64, 4, BS * 3), 256, PRJ_SMEM>>>();
    k_scores<<<dim3(D / 64, 4, BS * 2), 256, SCR_SMEM>>>();
    k_softmax<<<(2 * BS * D * 32 + 255) / 256, 256>>>();
    k_out<<<dim3(HW / 64, 4, BS), 256, OUT_SMEM>>>(Vs, out);
    k_final<<<1, 1>>>(out, out_size);
}